// round 5
// baseline (speedup 1.0000x reference)
#include <cuda_runtime.h>
#include <math.h>

#define BB 2
#define NN 1024
#define HH 128
#define WW 128
#define SEG 16
#define GPS (NN / SEG)   // gaussians per segment = 64

typedef unsigned long long u64;

// Scratch (static device globals — allowed)
__device__ float4 d_attr[BB * NN * 3];              // unsorted attrs
__device__ float  d_z[BB * NN];
__device__ float4 d_sorted[BB * NN * 3];            // [npx,npy,h00,h01][h11,op,r,g][b,z,-,-]
__device__ float4 d_seg_rgbd[BB * SEG * HH * WW];
__device__ float  d_seg_T[BB * SEG * HH * WW];
__device__ float  d_rgb[BB * 3 * HH * WW];
__device__ double d_acc[4];                         // l1_rgb, l1_depth, ssim, opac

__device__ __forceinline__ float warp_sum(float v) {
#pragma unroll
    for (int o = 16; o; o >>= 1) v += __shfl_down_sync(0xffffffffu, v, o);
    return v;
}

// ---- packed f32x2 helpers ----
__device__ __forceinline__ u64 pk2(float lo, float hi) {
    u64 r; asm("mov.b64 %0, {%1, %2};" : "=l"(r) : "f"(lo), "f"(hi)); return r;
}
__device__ __forceinline__ void upk2(float& lo, float& hi, u64 v) {
    asm("mov.b64 {%0, %1}, %2;" : "=f"(lo), "=f"(hi) : "l"(v));
}
__device__ __forceinline__ u64 add2(u64 a, u64 b) {
    u64 r; asm("add.rn.f32x2 %0, %1, %2;" : "=l"(r) : "l"(a), "l"(b)); return r;
}
__device__ __forceinline__ u64 mul2(u64 a, u64 b) {
    u64 r; asm("mul.rn.f32x2 %0, %1, %2;" : "=l"(r) : "l"(a), "l"(b)); return r;
}
__device__ __forceinline__ u64 fma2(u64 a, u64 b, u64 c) {
    u64 r; asm("fma.rn.f32x2 %0, %1, %2, %3;" : "=l"(r) : "l"(a), "l"(b), "l"(c)); return r;
}

__global__ void zero_kernel() {
    if (threadIdx.x < 4) d_acc[threadIdx.x] = 0.0;
}

// grid (4, BB) x 256: per-gaussian attribute compute + entropy partial
__global__ void prep_kernel(const float* __restrict__ g, const float* __restrict__ intr) {
    int b = blockIdx.y;
    int i = blockIdx.x * 256 + threadIdx.x;
    const float* gg = g + ((size_t)b * NN + i) * 38;
    float m0 = gg[0], m1 = gg[1], m2 = gg[2];
    float sx = gg[3], sy = gg[4], sz = gg[5];
    float qw = gg[6], qx = gg[7], qy = gg[8], qz = gg[9];
    float op = gg[10];
    float shr = gg[11], shg = gg[12], shb = gg[13];
    const float* I = intr + b * 9;
    float fx = I[0], cx = I[2], fy = I[4], cy = I[5];

    float zz = fmaxf(m2, 1e-4f);
    float px = fx * m0 / zz + cx;
    float py = fy * m1 / zz + cy;

    float R00 = 1.f - 2.f * (qy * qy + qz * qz), R01 = 2.f * (qx * qy - qw * qz), R02 = 2.f * (qx * qz + qw * qy);
    float R10 = 2.f * (qx * qy + qw * qz), R11 = 1.f - 2.f * (qx * qx + qz * qz), R12 = 2.f * (qy * qz - qw * qx);
    float R20 = 2.f * (qx * qz - qw * qy), R21 = 2.f * (qy * qz + qw * qx), R22 = 1.f - 2.f * (qx * qx + qy * qy);
    float A00 = R00 * sx, A01 = R01 * sy, A02 = R02 * sz;
    float A10 = R10 * sx, A11 = R11 * sy, A12 = R12 * sz;
    float A20 = R20 * sx, A21 = R21 * sy, A22 = R22 * sz;
    float C00 = A00 * A00 + A01 * A01 + A02 * A02;
    float C01 = A00 * A10 + A01 * A11 + A02 * A12;
    float C02 = A00 * A20 + A01 * A21 + A02 * A22;
    float C11 = A10 * A10 + A11 * A11 + A12 * A12;
    float C12 = A10 * A20 + A11 * A21 + A12 * A22;
    float C22 = A20 * A20 + A21 * A21 + A22 * A22;

    float zc = fmaxf(m2, 1e-6f);
    float zi = 1.f / zc, zi2 = zi * zi;
    float J00 = fx * zi, J02 = -fx * m0 * zi2;
    float J11 = fy * zi, J12 = -fy * m1 * zi2;
    float t0 = J00 * C00 + J02 * C02;
    float t1 = J00 * C01 + J02 * C12;
    float t2 = J00 * C02 + J02 * C22;
    float u0 = J11 * C01 + J12 * C02;
    float u1 = J11 * C11 + J12 * C12;
    float u2 = J11 * C12 + J12 * C22;
    float c00 = t0 * J00 + t2 * J02 + 0.3f;
    float c01 = t1 * J11 + t2 * J12;
    float c10 = u0 * J00 + u2 * J02;
    float c11 = u1 * J11 + u2 * J12 + 0.3f;
    float det = fmaxf(c00 * c11 - c01 * c10, 1e-8f);
    float inv00 = c11 / det, inv11 = c00 / det, inv01 = -c01 / det;

    const float C0c = 0.28209479177387814f;
    float cr = fminf(fmaxf(shr * C0c + 0.5f, 0.f), 1.f);
    float cg = fminf(fmaxf(shg * C0c + 0.5f, 0.f), 1.f);
    float cb = fminf(fmaxf(shb * C0c + 0.5f, 0.f), 1.f);

    const float L2E = 1.4426950408889634f;
    float4* dst = d_attr + ((size_t)b * NN + i) * 3;
    dst[0] = make_float4(-px, -py, -0.5f * inv00 * L2E, -inv01 * L2E);
    dst[1] = make_float4(-0.5f * inv11 * L2E, op, cr, cg);
    dst[2] = make_float4(cb, zz, 0.f, 0.f);
    d_z[b * NN + i] = zz;

    float o = fminf(fmaxf(op, 1e-6f), 1.f - 1e-6f);
    float ent = -(o * logf(o) + (1.f - o) * logf(1.f - o));

    __shared__ float red[8];
    float v = warp_sum(ent);
    int lane = threadIdx.x & 31, wid = threadIdx.x >> 5;
    if (lane == 0) red[wid] = v;
    __syncthreads();
    if (wid == 0) {
        float x = (lane < 8) ? red[lane] : 0.f;
        x = warp_sum(x);
        if (lane == 0) atomicAdd(&d_acc[3], (double)x);
    }
}

// grid (BB*8) x 128: stable rank by z + scatter attrs into sorted order
__global__ void rank_kernel() {
    int b = blockIdx.x >> 3;
    int s = blockIdx.x & 7;
    __shared__ float zs[NN];
    for (int k = threadIdx.x; k < NN; k += 128) zs[k] = d_z[b * NN + k];
    __syncthreads();
    int i = s * 128 + threadIdx.x;
    float zi = zs[i];
    int rank = 0;
#pragma unroll 8
    for (int j = 0; j < NN; j++) {
        float zj = zs[j];
        rank += (zj < zi) || (zj == zi && j < i);
    }
    const float4* src = d_attr + ((size_t)b * NN + i) * 3;
    float4* dst = d_sorted + ((size_t)b * NN + rank) * 3;
    dst[0] = src[0];
    dst[1] = src[1];
    dst[2] = src[2];
}

// grid (8, 8, BB*SEG) x 128; each thread composites 2 pixels (y, y+8) packed f32x2
__global__ void render_kernel() {
    int bz = blockIdx.z;
    int b = bz >> 4;       // SEG == 16
    int s = bz & 15;
    int t = threadIdx.x;
    int tx = t & 15, ty = t >> 4;
    int x = blockIdx.x * 16 + tx;
    int y0 = blockIdx.y * 16 + ty;          // second pixel at y0+8
    float xf = (float)x, yf0 = (float)y0, yf1 = (float)(y0 + 8);
    u64 xp = pk2(xf, xf);
    u64 yp = pk2(yf0, yf1);

    __shared__ float4 sg[GPS * 5];          // duplicated layout, 5KB
    const float4* base = d_sorted + ((size_t)b * NN + s * GPS) * 3;
    for (int k = t; k < GPS; k += 128) {
        float4 q0 = base[k * 3 + 0];
        float4 q1 = base[k * 3 + 1];
        float4 q2 = base[k * 3 + 2];
        sg[k * 5 + 0] = make_float4(q0.x, q0.x, q0.y, q0.y);   // npx2, npy2
        sg[k * 5 + 1] = make_float4(q0.z, q0.z, q0.w, q0.w);   // h002, h012
        sg[k * 5 + 2] = make_float4(q1.x, q1.x, q1.y, q1.y);   // h112, op2
        sg[k * 5 + 3] = make_float4(q1.z, q1.z, q1.w, q1.w);   // r2,   g2
        sg[k * 5 + 4] = make_float4(q2.x, q2.x, q2.y, q2.y);   // b2,   z2
    }
    __syncthreads();

    u64 T = pk2(1.f, 1.f);
    u64 aR = 0ull, aG = 0ull, aB = 0ull, aD = 0ull;
    const u64 negonep = pk2(-1.f, -1.f);
    const float CLMP = -14.4269504088896f;   // -10 * log2(e)

    const ulonglong2* sp = (const ulonglong2*)sg;
#pragma unroll 4
    for (int j = 0; j < GPS; j++) {
        ulonglong2 w0 = sp[j * 5 + 0];
        ulonglong2 w1 = sp[j * 5 + 1];
        ulonglong2 w2 = sp[j * 5 + 2];
        ulonglong2 w3 = sp[j * 5 + 3];
        ulonglong2 w4 = sp[j * 5 + 4];
        u64 dx = add2(xp, w0.x);
        u64 dy = add2(yp, w0.y);
        u64 t2 = mul2(w1.y, dy);           // h01*dy
        u64 uu = fma2(w1.x, dx, t2);       // h00*dx + h01*dy
        u64 t1 = mul2(w2.x, dy);           // h11*dy
        u64 t1b = mul2(t1, dy);            // h11*dy*dy
        u64 pw = fma2(dx, uu, t1b);        // log2-domain power (<= ~0)
        float p0, p1;
        upk2(p0, p1, pw);
        p0 = fmaxf(p0, CLMP);
        p1 = fmaxf(p1, CLMP);
        float e0, e1;
        asm("ex2.approx.f32 %0, %1;" : "=f"(e0) : "f"(p0));
        asm("ex2.approx.f32 %0, %1;" : "=f"(e1) : "f"(p1));
        u64 ep = pk2(e0, e1);
        u64 ap = mul2(ep, w2.y);           // * opacity
        float a0, a1;
        upk2(a0, a1, ap);
        a0 = fminf(a0, 0.99f);
        a1 = fminf(a1, 0.99f);
        u64 am = pk2(a0, a1);
        u64 w = mul2(T, am);               // weight = T*a
        T = fma2(w, negonep, T);           // T -= T*a
        aR = fma2(w, w3.x, aR);
        aG = fma2(w, w3.y, aG);
        aB = fma2(w, w4.x, aB);
        aD = fma2(w, w4.y, aD);
    }

    float r0, r1, g0, g1, b0, b1, dd0, dd1, T0, T1;
    upk2(r0, r1, aR); upk2(g0, g1, aG); upk2(b0, b1, aB); upk2(dd0, dd1, aD); upk2(T0, T1, T);
    int segbase = (b * SEG + s) * (HH * WW);
    int o0 = segbase + y0 * WW + x;
    int o1 = segbase + (y0 + 8) * WW + x;
    d_seg_rgbd[o0] = make_float4(r0, g0, b0, dd0);
    d_seg_rgbd[o1] = make_float4(r1, g1, b1, dd1);
    d_seg_T[o0] = T0;
    d_seg_T[o1] = T1;
}

// one thread per (pixel, segment); 16-lane shuffle scan merge
__global__ void merge_kernel(const float* __restrict__ target_rgb,
                             const float* __restrict__ target_depth) {
    int idx = blockIdx.x * 256 + threadIdx.x;
    int s = idx & 15;
    int g = idx >> 4;
    int hw = HH * WW;
    int b = g / hw;
    int pix = g % hw;
    int o = (b * SEG + s) * hw + pix;
    float4 c = d_seg_rgbd[o];
    float t = d_seg_T[o];

    // inclusive prefix product of t within 16-lane group
    float pre = t;
    int sub = threadIdx.x & 15;
#pragma unroll
    for (int d = 1; d < 16; d <<= 1) {
        float v = __shfl_up_sync(0xffffffffu, pre, d, 16);
        if (sub >= d) pre *= v;
    }
    // exclusive prefix (transmittance before this segment)
    float Texc = __shfl_up_sync(0xffffffffu, pre, 1, 16);
    if (sub == 0) Texc = 1.f;
    c.x *= Texc; c.y *= Texc; c.z *= Texc; c.w *= Texc;
#pragma unroll
    for (int d = 8; d; d >>= 1) {
        c.x += __shfl_down_sync(0xffffffffu, c.x, d, 16);
        c.y += __shfl_down_sync(0xffffffffu, c.y, d, 16);
        c.z += __shfl_down_sync(0xffffffffu, c.z, d, 16);
        c.w += __shfl_down_sync(0xffffffffu, c.w, d, 16);
    }

    float l1 = 0.f, l1d = 0.f;
    if (sub == 0) {
        float R = fminf(fmaxf(c.x, 0.f), 1.f);
        float G = fminf(fmaxf(c.y, 0.f), 1.f);
        float Bc = fminf(fmaxf(c.z, 0.f), 1.f);
        d_rgb[(b * 3 + 0) * hw + pix] = R;
        d_rgb[(b * 3 + 1) * hw + pix] = G;
        d_rgb[(b * 3 + 2) * hw + pix] = Bc;
        l1 = fabsf(R - target_rgb[(b * 3 + 0) * hw + pix]) +
             fabsf(G - target_rgb[(b * 3 + 1) * hw + pix]) +
             fabsf(Bc - target_rgb[(b * 3 + 2) * hw + pix]);
        l1d = fabsf(c.w - target_depth[b * hw + pix]);
    }

    __shared__ float red[8];
    int lane = threadIdx.x & 31, wid = threadIdx.x >> 5;
    float v = warp_sum(l1);
    if (lane == 0) red[wid] = v;
    __syncthreads();
    if (wid == 0) {
        float sm = (lane < 8) ? red[lane] : 0.f;
        sm = warp_sum(sm);
        if (lane == 0) atomicAdd(&d_acc[0], (double)sm);
    }
    __syncthreads();
    v = warp_sum(l1d);
    if (lane == 0) red[wid] = v;
    __syncthreads();
    if (wid == 0) {
        float sm = (lane < 8) ? red[lane] : 0.f;
        sm = warp_sum(sm);
        if (lane == 0) atomicAdd(&d_acc[1], (double)sm);
    }
}

// fused 7x7 depthwise SSIM + mean reduce
__global__ void ssim_kernel(const float* __restrict__ target_rgb) {
    const float GW[7] = {0.03663229f, 0.11128005f, 0.21674607f, 0.27068313f,
                         0.21674607f, 0.11128005f, 0.03663229f};
    int idx = blockIdx.x * 256 + threadIdx.x;
    float val = 0.f;
    if (idx < BB * 3 * HH * WW) {
        int x = idx % WW;
        int y = (idx / WW) % HH;
        int bc = idx / (HH * WW);
        const float* i1 = d_rgb + (size_t)bc * HH * WW;
        const float* i2 = target_rgb + (size_t)bc * HH * WW;

        float m1 = 0.f, m2 = 0.f, e11 = 0.f, e22 = 0.f, e12 = 0.f;
        if (x >= 3 && x < WW - 3 && y >= 3 && y < HH - 3) {
#pragma unroll
            for (int ky = 0; ky < 7; ky++) {
                int yy = y + ky - 3;
                float wy = GW[ky];
#pragma unroll
                for (int kx = 0; kx < 7; kx++) {
                    int xx = x + kx - 3;
                    float w = wy * GW[kx];
                    float v1 = i1[yy * WW + xx];
                    float v2 = i2[yy * WW + xx];
                    m1 = fmaf(w, v1, m1);
                    m2 = fmaf(w, v2, m2);
                    e11 = fmaf(w * v1, v1, e11);
                    e22 = fmaf(w * v2, v2, e22);
                    e12 = fmaf(w * v1, v2, e12);
                }
            }
        } else {
#pragma unroll
            for (int ky = 0; ky < 7; ky++) {
                int yy = y + ky - 3;
                if (yy < 0 || yy >= HH) continue;
                float wy = GW[ky];
#pragma unroll
                for (int kx = 0; kx < 7; kx++) {
                    int xx = x + kx - 3;
                    if (xx < 0 || xx >= WW) continue;
                    float w = wy * GW[kx];
                    float v1 = i1[yy * WW + xx];
                    float v2 = i2[yy * WW + xx];
                    m1 = fmaf(w, v1, m1);
                    m2 = fmaf(w, v2, m2);
                    e11 = fmaf(w * v1, v1, e11);
                    e22 = fmaf(w * v2, v2, e22);
                    e12 = fmaf(w * v1, v2, e12);
                }
            }
        }
        float s1 = e11 - m1 * m1;
        float s2 = e22 - m2 * m2;
        float s12 = e12 - m1 * m2;
        const float C1 = 0.0001f, C2 = 0.0009f;
        val = (2.f * m1 * m2 + C1) * (2.f * s12 + C2) /
              ((m1 * m1 + m2 * m2 + C1) * (s1 + s2 + C2));
    }
    __shared__ float red[8];
    int lane = threadIdx.x & 31, wid = threadIdx.x >> 5;
    float v = warp_sum(val);
    if (lane == 0) red[wid] = v;
    __syncthreads();
    if (wid == 0) {
        float x2 = (lane < 8) ? red[lane] : 0.f;
        x2 = warp_sum(x2);
        if (lane == 0) atomicAdd(&d_acc[2], (double)x2);
    }
}

__global__ void final_kernel(float* __restrict__ out) {
    double l1rgb = d_acc[0] / (double)(BB * 3 * HH * WW);
    double l1d = d_acc[1] / (double)(BB * HH * WW);
    double ssim = d_acc[2] / (double)(BB * 3 * HH * WW);
    double opac = d_acc[3] / (double)(BB * NN);
    out[0] = (float)(0.8 * l1rgb + 0.2 * (1.0 - ssim) + 0.5 * l1d + 0.01 * opac);
}

extern "C" void kernel_launch(void* const* d_in, const int* in_sizes, int n_in,
                              void* d_out, int out_size) {
    const float* gaussians = (const float*)d_in[0];
    const float* intrinsics = (const float*)d_in[1];
    const float* target_rgb = (const float*)d_in[2];
    const float* target_depth = (const float*)d_in[3];
    float* out = (float*)d_out;

    zero_kernel<<<1, 32>>>();
    prep_kernel<<<dim3(4, BB), 256>>>(gaussians, intrinsics);
    rank_kernel<<<BB * 8, 128>>>();
    render_kernel<<<dim3(8, 8, BB * SEG), 128>>>();
    merge_kernel<<<(BB * HH * WW * SEG) / 256, 256>>>(target_rgb, target_depth);
    ssim_kernel<<<(BB * 3 * HH * WW + 255) / 256, 256>>>(target_rgb);
    final_kernel<<<1, 1>>>(out);
}

// round 8
// speedup vs baseline: 1.2024x; 1.2024x over previous
#include <cuda_runtime.h>
#include <math.h>

#define BB 2
#define NN 1024
#define HH 128
#define WW 128
#define SEG 8
#define GPS (NN / SEG)   // 128 gaussians per segment

typedef unsigned long long u64;

// Scratch (static device globals — allowed)
__device__ float4 d_attr[BB * NN * 3];
__device__ float  d_z[BB * NN];
__device__ float4 d_sorted[BB * NN * 3];   // [npx,npy,h00,h01][h11,op,r,g][b,z,lam,-]
__device__ float4 d_seg_rgbd[BB * SEG * HH * WW];
__device__ float  d_seg_T[BB * SEG * HH * WW];
__device__ float  d_rgb[BB * 3 * HH * WW];
__device__ float  d_p_ent[8];
__device__ float  d_p_l1[1024];
__device__ float  d_p_l1d[1024];
__device__ float  d_p_ssim[384];

__device__ __forceinline__ float warp_sum(float v) {
#pragma unroll
    for (int o = 16; o; o >>= 1) v += __shfl_down_sync(0xffffffffu, v, o);
    return v;
}
__device__ __forceinline__ float block_sum256(float v, float* red) {
    int lane = threadIdx.x & 31, wid = threadIdx.x >> 5;
    v = warp_sum(v);
    if (lane == 0) red[wid] = v;
    __syncthreads();
    float s = 0.f;
    if (wid == 0) {
        s = (lane < 8) ? red[lane] : 0.f;
        s = warp_sum(s);
    }
    __syncthreads();
    return s;  // valid in thread 0
}

// ---- packed f32x2 helpers ----
__device__ __forceinline__ u64 pk2(float lo, float hi) {
    u64 r; asm("mov.b64 %0, {%1, %2};" : "=l"(r) : "f"(lo), "f"(hi)); return r;
}
__device__ __forceinline__ void upk2(float& lo, float& hi, u64 v) {
    asm("mov.b64 {%0, %1}, %2;" : "=f"(lo), "=f"(hi) : "l"(v));
}
__device__ __forceinline__ u64 add2(u64 a, u64 b) {
    u64 r; asm("add.rn.f32x2 %0, %1, %2;" : "=l"(r) : "l"(a), "l"(b)); return r;
}
__device__ __forceinline__ u64 mul2(u64 a, u64 b) {
    u64 r; asm("mul.rn.f32x2 %0, %1, %2;" : "=l"(r) : "l"(a), "l"(b)); return r;
}
__device__ __forceinline__ u64 fma2(u64 a, u64 b, u64 c) {
    u64 r; asm("fma.rn.f32x2 %0, %1, %2, %3;" : "=l"(r) : "l"(a), "l"(b), "l"(c)); return r;
}

// grid (4, BB) x 256
__global__ void prep_kernel(const float* __restrict__ g, const float* __restrict__ intr) {
    int b = blockIdx.y;
    int i = blockIdx.x * 256 + threadIdx.x;
    const float* gg = g + ((size_t)b * NN + i) * 38;
    float m0 = gg[0], m1 = gg[1], m2 = gg[2];
    float sx = gg[3], sy = gg[4], sz = gg[5];
    float qw = gg[6], qx = gg[7], qy = gg[8], qz = gg[9];
    float op = gg[10];
    float shr = gg[11], shg = gg[12], shb = gg[13];
    const float* I = intr + b * 9;
    float fx = I[0], cx = I[2], fy = I[4], cy = I[5];

    float zz = fmaxf(m2, 1e-4f);
    float px = fx * m0 / zz + cx;
    float py = fy * m1 / zz + cy;

    float R00 = 1.f - 2.f * (qy * qy + qz * qz), R01 = 2.f * (qx * qy - qw * qz), R02 = 2.f * (qx * qz + qw * qy);
    float R10 = 2.f * (qx * qy + qw * qz), R11 = 1.f - 2.f * (qx * qx + qz * qz), R12 = 2.f * (qy * qz - qw * qx);
    float R20 = 2.f * (qx * qz - qw * qy), R21 = 2.f * (qy * qz + qw * qx), R22 = 1.f - 2.f * (qx * qx + qy * qy);
    float A00 = R00 * sx, A01 = R01 * sy, A02 = R02 * sz;
    float A10 = R10 * sx, A11 = R11 * sy, A12 = R12 * sz;
    float A20 = R20 * sx, A21 = R21 * sy, A22 = R22 * sz;
    float C00 = A00 * A00 + A01 * A01 + A02 * A02;
    float C01 = A00 * A10 + A01 * A11 + A02 * A12;
    float C02 = A00 * A20 + A01 * A21 + A02 * A22;
    float C11 = A10 * A10 + A11 * A11 + A12 * A12;
    float C12 = A10 * A20 + A11 * A21 + A12 * A22;
    float C22 = A20 * A20 + A21 * A21 + A22 * A22;

    float zc = fmaxf(m2, 1e-6f);
    float zi = 1.f / zc, zi2 = zi * zi;
    float J00 = fx * zi, J02 = -fx * m0 * zi2;
    float J11 = fy * zi, J12 = -fy * m1 * zi2;
    float t0 = J00 * C00 + J02 * C02;
    float t1 = J00 * C01 + J02 * C12;
    float t2 = J00 * C02 + J02 * C22;
    float u0 = J11 * C01 + J12 * C02;
    float u1 = J11 * C11 + J12 * C12;
    float u2 = J11 * C12 + J12 * C22;
    float c00 = t0 * J00 + t2 * J02 + 0.3f;
    float c01 = t1 * J11 + t2 * J12;
    float c10 = u0 * J00 + u2 * J02;
    float c11 = u1 * J11 + u2 * J12 + 0.3f;
    float det = fmaxf(c00 * c11 - c01 * c10, 1e-8f);
    float inv00 = c11 / det, inv11 = c00 / det, inv01 = -c01 / det;

    const float C0c = 0.28209479177387814f;
    float cr = fminf(fmaxf(shr * C0c + 0.5f, 0.f), 1.f);
    float cg = fminf(fmaxf(shg * C0c + 0.5f, 0.f), 1.f);
    float cb = fminf(fmaxf(shb * C0c + 0.5f, 0.f), 1.f);

    const float L2E = 1.4426950408889634f;
    // log2-domain conic: Q(d) = Aq*dx^2 + 2Bq*dx*dy + Cq*dy^2; pw = -Q(d)
    float Aq = 0.5f * inv00 * L2E;
    float Cq = 0.5f * inv11 * L2E;
    float Bq = 0.5f * inv01 * L2E;
    float half_sum = 0.5f * (Aq + Cq);
    float half_dif = 0.5f * (Aq - Cq);
    float lam = half_sum - sqrtf(half_dif * half_dif + Bq * Bq);
    lam = fmaxf(lam, 0.f);

    float4* dst = d_attr + ((size_t)b * NN + i) * 3;
    dst[0] = make_float4(-px, -py, -Aq, -2.f * Bq);
    dst[1] = make_float4(-Cq, op, cr, cg);
    dst[2] = make_float4(cb, zz, lam, 0.f);
    d_z[b * NN + i] = zz;

    float o = fminf(fmaxf(op, 1e-6f), 1.f - 1e-6f);
    float ent = -(o * logf(o) + (1.f - o) * logf(1.f - o));

    __shared__ float red[8];
    float s = block_sum256(ent, red);
    if (threadIdx.x == 0) d_p_ent[blockIdx.y * 4 + blockIdx.x] = s;
}

// grid (BB*8) x 128: stable rank by z + scatter
__global__ void rank_kernel() {
    int b = blockIdx.x >> 3;
    int s = blockIdx.x & 7;
    __shared__ float zs[NN];
    for (int k = threadIdx.x; k < NN; k += 128) zs[k] = d_z[b * NN + k];
    __syncthreads();
    int i = s * 128 + threadIdx.x;
    float zi = zs[i];
    int rank = 0;
#pragma unroll 8
    for (int j = 0; j < NN; j++) {
        float zj = zs[j];
        rank += (zj < zi) || (zj == zi && j < i);
    }
    const float4* src = d_attr + ((size_t)b * NN + i) * 3;
    float4* dst = d_sorted + ((size_t)b * NN + rank) * 3;
    dst[0] = src[0];
    dst[1] = src[1];
    dst[2] = src[2];
}

// grid (8, 8, BB*SEG) x 128; 2 pixels/thread packed f32x2; per-tile far/near culling
__global__ void render_kernel() {
    int bz = blockIdx.z;
    int b = bz >> 3;       // SEG == 8
    int s = bz & 7;
    int t = threadIdx.x;
    int tx = t & 15, ty = t >> 4;
    int x = blockIdx.x * 16 + tx;
    int y0 = blockIdx.y * 16 + ty;
    float xf = (float)x, yf0 = (float)y0, yf1 = (float)(y0 + 8);
    u64 xp = pk2(xf, xf);
    u64 yp = pk2(yf0, yf1);

    __shared__ float4 sg[GPS * 5];          // duplicated packed layout, 10KB
    __shared__ unsigned smask[GPS / 32];    // near bits
    const float4* base = d_sorted + ((size_t)b * NN + s * GPS) * 3;
    {
        // each thread stages + classifies one gaussian (GPS == blockDim)
        float4 q0 = base[t * 3 + 0];
        float4 q1 = base[t * 3 + 1];
        float4 q2 = base[t * 3 + 2];
        sg[t * 5 + 0] = make_float4(q0.x, q0.x, q0.y, q0.y);   // npx2, npy2
        sg[t * 5 + 1] = make_float4(q0.z, q0.z, q0.w, q0.w);   // h002, h012
        sg[t * 5 + 2] = make_float4(q1.x, q1.x, q1.y, q1.y);   // h112, op2
        sg[t * 5 + 3] = make_float4(q1.z, q1.z, q1.w, q1.w);   // r2,   g2
        sg[t * 5 + 4] = make_float4(q2.x, q2.x, q2.y, q2.y);   // b2,   z2

        float pxx = -q0.x, pyy = -q0.y;
        float rx0 = (float)(blockIdx.x * 16), ry0 = (float)(blockIdx.y * 16);
        float dmx = fmaxf(0.f, fmaxf(rx0 - pxx, pxx - (rx0 + 15.f)));
        float dmy = fmaxf(0.f, fmaxf(ry0 - pyy, pyy - (ry0 + 15.f)));
        bool nearg = q2.z * (dmx * dmx + dmy * dmy) < 14.4269504088896f;
        unsigned bal = __ballot_sync(0xffffffffu, nearg);
        if ((t & 31) == 0) smask[t >> 5] = bal;
    }
    __syncthreads();

    u64 T = pk2(1.f, 1.f);
    u64 aR = 0ull, aG = 0ull, aB = 0ull, aD = 0ull;
    const u64 negonep = pk2(-1.f, -1.f);
    const float AFAR = 4.5399929762484854e-05f;   // exp(-10)
    const u64 afarp = pk2(AFAR, AFAR);
    const float CLMP = -14.4269504088896f;         // -10 * log2(e)

    unsigned m0w = smask[0], m1w = smask[1], m2w = smask[2], m3w = smask[3];
    const ulonglong2* sp = (const ulonglong2*)sg;
#pragma unroll 2
    for (int j = 0; j < GPS; j++) {
        unsigned mw = (j < 64) ? ((j < 32) ? m0w : m1w) : ((j < 96) ? m2w : m3w);
        bool nearg = (mw >> (j & 31)) & 1u;
        ulonglong2 w2 = sp[j * 5 + 2];
        ulonglong2 w3 = sp[j * 5 + 3];
        ulonglong2 w4 = sp[j * 5 + 4];
        u64 am;
        if (nearg) {
            ulonglong2 w0 = sp[j * 5 + 0];
            ulonglong2 w1 = sp[j * 5 + 1];
            u64 dx = add2(xp, w0.x);
            u64 dy = add2(yp, w0.y);
            u64 t2 = mul2(w1.y, dy);
            u64 uu = fma2(w1.x, dx, t2);
            u64 t1 = mul2(w2.x, dy);
            u64 t1b = mul2(t1, dy);
            u64 pw = fma2(dx, uu, t1b);
            float p0, p1;
            upk2(p0, p1, pw);
            p0 = fmaxf(p0, CLMP);
            p1 = fmaxf(p1, CLMP);
            float e0, e1;
            asm("ex2.approx.f32 %0, %1;" : "=f"(e0) : "f"(p0));
            asm("ex2.approx.f32 %0, %1;" : "=f"(e1) : "f"(p1));
            u64 ep = pk2(e0, e1);
            u64 ap = mul2(ep, w2.y);
            float a0, a1;
            upk2(a0, a1, ap);
            a0 = fminf(a0, 0.99f);
            a1 = fminf(a1, 0.99f);
            am = pk2(a0, a1);
        } else {
            am = mul2(afarp, w2.y);        // exp(-10)*opac, pixel-independent
        }
        u64 w = mul2(T, am);
        T = fma2(w, negonep, T);
        aR = fma2(w, w3.x, aR);
        aG = fma2(w, w3.y, aG);
        aB = fma2(w, w4.x, aB);
        aD = fma2(w, w4.y, aD);
    }

    float r0, r1, g0, g1, b0, b1, dd0, dd1, T0, T1;
    upk2(r0, r1, aR); upk2(g0, g1, aG); upk2(b0, b1, aB); upk2(dd0, dd1, aD); upk2(T0, T1, T);
    int segbase = (b * SEG + s) * (HH * WW);
    int o0 = segbase + y0 * WW + x;
    int o1 = segbase + (y0 + 8) * WW + x;
    d_seg_rgbd[o0] = make_float4(r0, g0, b0, dd0);
    d_seg_rgbd[o1] = make_float4(r1, g1, b1, dd1);
    d_seg_T[o0] = T0;
    d_seg_T[o1] = T1;
}

// grid 1024 x 256: one thread per (pixel, segment); 8-lane shuffle scan merge
__global__ void merge_kernel(const float* __restrict__ target_rgb,
                             const float* __restrict__ target_depth) {
    int idx = blockIdx.x * 256 + threadIdx.x;
    int s = idx & 7;
    int g = idx >> 3;
    int hw = HH * WW;
    int b = g / hw;
    int pix = g % hw;
    int o = (b * SEG + s) * hw + pix;
    float4 c = d_seg_rgbd[o];
    float t = d_seg_T[o];

    float pre = t;
    int sub = threadIdx.x & 7;
#pragma unroll
    for (int d = 1; d < 8; d <<= 1) {
        float v = __shfl_up_sync(0xffffffffu, pre, d, 8);
        if (sub >= d) pre *= v;
    }
    float Texc = __shfl_up_sync(0xffffffffu, pre, 1, 8);
    if (sub == 0) Texc = 1.f;
    c.x *= Texc; c.y *= Texc; c.z *= Texc; c.w *= Texc;
#pragma unroll
    for (int d = 4; d; d >>= 1) {
        c.x += __shfl_down_sync(0xffffffffu, c.x, d, 8);
        c.y += __shfl_down_sync(0xffffffffu, c.y, d, 8);
        c.z += __shfl_down_sync(0xffffffffu, c.z, d, 8);
        c.w += __shfl_down_sync(0xffffffffu, c.w, d, 8);
    }

    float l1 = 0.f, l1d = 0.f;
    if (sub == 0) {
        float R = fminf(fmaxf(c.x, 0.f), 1.f);
        float G = fminf(fmaxf(c.y, 0.f), 1.f);
        float Bc = fminf(fmaxf(c.z, 0.f), 1.f);
        d_rgb[(b * 3 + 0) * hw + pix] = R;
        d_rgb[(b * 3 + 1) * hw + pix] = G;
        d_rgb[(b * 3 + 2) * hw + pix] = Bc;
        l1 = fabsf(R - target_rgb[(b * 3 + 0) * hw + pix]) +
             fabsf(G - target_rgb[(b * 3 + 1) * hw + pix]) +
             fabsf(Bc - target_rgb[(b * 3 + 2) * hw + pix]);
        l1d = fabsf(c.w - target_depth[b * hw + pix]);
    }

    __shared__ float red[8];
    float s0 = block_sum256(l1, red);
    if (threadIdx.x == 0) d_p_l1[blockIdx.x] = s0;
    float s1 = block_sum256(l1d, red);
    if (threadIdx.x == 0) d_p_l1d[blockIdx.x] = s1;
}

// fused 7x7 depthwise SSIM + partial reduce
__global__ void ssim_kernel(const float* __restrict__ target_rgb) {
    const float GW[7] = {0.03663229f, 0.11128005f, 0.21674607f, 0.27068313f,
                         0.21674607f, 0.11128005f, 0.03663229f};
    int idx = blockIdx.x * 256 + threadIdx.x;
    float val = 0.f;
    {
        int x = idx % WW;
        int y = (idx / WW) % HH;
        int bc = idx / (HH * WW);
        const float* i1 = d_rgb + (size_t)bc * HH * WW;
        const float* i2 = target_rgb + (size_t)bc * HH * WW;

        float m1 = 0.f, m2 = 0.f, e11 = 0.f, e22 = 0.f, e12 = 0.f;
        if (x >= 3 && x < WW - 3 && y >= 3 && y < HH - 3) {
#pragma unroll
            for (int ky = 0; ky < 7; ky++) {
                int yy = y + ky - 3;
                float wy = GW[ky];
#pragma unroll
                for (int kx = 0; kx < 7; kx++) {
                    int xx = x + kx - 3;
                    float w = wy * GW[kx];
                    float v1 = i1[yy * WW + xx];
                    float v2 = i2[yy * WW + xx];
                    m1 = fmaf(w, v1, m1);
                    m2 = fmaf(w, v2, m2);
                    e11 = fmaf(w * v1, v1, e11);
                    e22 = fmaf(w * v2, v2, e22);
                    e12 = fmaf(w * v1, v2, e12);
                }
            }
        } else {
#pragma unroll
            for (int ky = 0; ky < 7; ky++) {
                int yy = y + ky - 3;
                if (yy < 0 || yy >= HH) continue;
                float wy = GW[ky];
#pragma unroll
                for (int kx = 0; kx < 7; kx++) {
                    int xx = x + kx - 3;
                    if (xx < 0 || xx >= WW) continue;
                    float w = wy * GW[kx];
                    float v1 = i1[yy * WW + xx];
                    float v2 = i2[yy * WW + xx];
                    m1 = fmaf(w, v1, m1);
                    m2 = fmaf(w, v2, m2);
                    e11 = fmaf(w * v1, v1, e11);
                    e22 = fmaf(w * v2, v2, e22);
                    e12 = fmaf(w * v1, v2, e12);
                }
            }
        }
        float s1 = e11 - m1 * m1;
        float s2 = e22 - m2 * m2;
        float s12 = e12 - m1 * m2;
        const float C1 = 0.0001f, C2 = 0.0009f;
        val = (2.f * m1 * m2 + C1) * (2.f * s12 + C2) /
              ((m1 * m1 + m2 * m2 + C1) * (s1 + s2 + C2));
    }
    __shared__ float red[8];
    float s = block_sum256(val, red);
    if (threadIdx.x == 0) d_p_ssim[blockIdx.x] = s;
}

// single block 256 threads: sum partials (double accum), combine
__global__ void final_kernel(float* __restrict__ out) {
    int t = threadIdx.x;
    double a0 = 0.0, a1 = 0.0, a2 = 0.0, a3 = 0.0;
    for (int i = t; i < 1024; i += 256) { a0 += (double)d_p_l1[i]; a1 += (double)d_p_l1d[i]; }
    for (int i = t; i < 384; i += 256) a2 += (double)d_p_ssim[i];
    if (t < 8) a3 = (double)d_p_ent[t];

    __shared__ double sm0[256], sm1[256], sm2[256], sm3[256];
    sm0[t] = a0; sm1[t] = a1; sm2[t] = a2; sm3[t] = a3;
    __syncthreads();
    for (int o = 128; o; o >>= 1) {
        if (t < o) {
            sm0[t] += sm0[t + o];
            sm1[t] += sm1[t + o];
            sm2[t] += sm2[t + o];
            sm3[t] += sm3[t + o];
        }
        __syncthreads();
    }
    if (t == 0) {
        double l1rgb = sm0[0] / (double)(BB * 3 * HH * WW);
        double l1d = sm1[0] / (double)(BB * HH * WW);
        double ssim = sm2[0] / (double)(BB * 3 * HH * WW);
        double opac = sm3[0] / (double)(BB * NN);
        out[0] = (float)(0.8 * l1rgb + 0.2 * (1.0 - ssim) + 0.5 * l1d + 0.01 * opac);
    }
}

extern "C" void kernel_launch(void* const* d_in, const int* in_sizes, int n_in,
                              void* d_out, int out_size) {
    const float* gaussians = (const float*)d_in[0];
    const float* intrinsics = (const float*)d_in[1];
    const float* target_rgb = (const float*)d_in[2];
    const float* target_depth = (const float*)d_in[3];
    float* out = (float*)d_out;

    prep_kernel<<<dim3(4, BB), 256>>>(gaussians, intrinsics);
    rank_kernel<<<BB * 8, 128>>>();
    render_kernel<<<dim3(8, 8, BB * SEG), 128>>>();
    merge_kernel<<<(BB * HH * WW * SEG) / 256, 256>>>(target_rgb, target_depth);
    ssim_kernel<<<(BB * 3 * HH * WW) / 256, 256>>>(target_rgb);
    final_kernel<<<1, 256>>>(out);
}

// round 9
// speedup vs baseline: 1.4214x; 1.1822x over previous
#include <cuda_runtime.h>
#include <math.h>

#define BB 2
#define NN 1024
#define HH 128
#define WW 128
#define SEG 8
#define GPS (NN / SEG)   // 128 gaussians per segment

typedef unsigned long long u64;

// Scratch (static device globals — allowed)
__device__ float4 d_attr[BB * NN * 3];
__device__ float  d_z[BB * NN];
__device__ float4 d_sorted[BB * NN * 3];   // [npx,npy,h00,h01][h11,op,r,g][b,z,lam,-]
__device__ float4 d_pfQ[BB * SEG * (GPS + 1)];   // Q = S/P (as-if-all-far prefix)
__device__ float2 d_pfPP[BB * SEG * (GPS + 1)];  // (P, 1/P)
__device__ float4 d_seg_rgbd[BB * SEG * HH * WW];
__device__ float  d_seg_T[BB * SEG * HH * WW];
__device__ float  d_rgb[BB * 3 * HH * WW];
__device__ float  d_p_ent[8];
__device__ float  d_p_l1[1024];
__device__ float  d_p_l1d[1024];
__device__ float  d_p_ssim[384];

#define AFARC 4.5399929762484854e-05f   // exp(-10)

__device__ __forceinline__ float warp_sum(float v) {
#pragma unroll
    for (int o = 16; o; o >>= 1) v += __shfl_down_sync(0xffffffffu, v, o);
    return v;
}
__device__ __forceinline__ float block_sum256(float v, float* red) {
    int lane = threadIdx.x & 31, wid = threadIdx.x >> 5;
    v = warp_sum(v);
    if (lane == 0) red[wid] = v;
    __syncthreads();
    float s = 0.f;
    if (wid == 0) {
        s = (lane < 8) ? red[lane] : 0.f;
        s = warp_sum(s);
    }
    __syncthreads();
    return s;  // valid in thread 0
}

// ---- packed f32x2 helpers ----
__device__ __forceinline__ u64 pk2(float lo, float hi) {
    u64 r; asm("mov.b64 %0, {%1, %2};" : "=l"(r) : "f"(lo), "f"(hi)); return r;
}
__device__ __forceinline__ void upk2(float& lo, float& hi, u64 v) {
    asm("mov.b64 {%0, %1}, %2;" : "=f"(lo), "=f"(hi) : "l"(v));
}
__device__ __forceinline__ u64 add2(u64 a, u64 b) {
    u64 r; asm("add.rn.f32x2 %0, %1, %2;" : "=l"(r) : "l"(a), "l"(b)); return r;
}
__device__ __forceinline__ u64 mul2(u64 a, u64 b) {
    u64 r; asm("mul.rn.f32x2 %0, %1, %2;" : "=l"(r) : "l"(a), "l"(b)); return r;
}
__device__ __forceinline__ u64 fma2(u64 a, u64 b, u64 c) {
    u64 r; asm("fma.rn.f32x2 %0, %1, %2, %3;" : "=l"(r) : "l"(a), "l"(b), "l"(c)); return r;
}

// grid (4, BB) x 256
__global__ void prep_kernel(const float* __restrict__ g, const float* __restrict__ intr) {
    int b = blockIdx.y;
    int i = blockIdx.x * 256 + threadIdx.x;
    const float* gg = g + ((size_t)b * NN + i) * 38;
    float m0 = gg[0], m1 = gg[1], m2 = gg[2];
    float sx = gg[3], sy = gg[4], sz = gg[5];
    float qw = gg[6], qx = gg[7], qy = gg[8], qz = gg[9];
    float op = gg[10];
    float shr = gg[11], shg = gg[12], shb = gg[13];
    const float* I = intr + b * 9;
    float fx = I[0], cx = I[2], fy = I[4], cy = I[5];

    float zz = fmaxf(m2, 1e-4f);
    float px = fx * m0 / zz + cx;
    float py = fy * m1 / zz + cy;

    float R00 = 1.f - 2.f * (qy * qy + qz * qz), R01 = 2.f * (qx * qy - qw * qz), R02 = 2.f * (qx * qz + qw * qy);
    float R10 = 2.f * (qx * qy + qw * qz), R11 = 1.f - 2.f * (qx * qx + qz * qz), R12 = 2.f * (qy * qz - qw * qx);
    float R20 = 2.f * (qx * qz - qw * qy), R21 = 2.f * (qy * qz + qw * qx), R22 = 1.f - 2.f * (qx * qx + qy * qy);
    float A00 = R00 * sx, A01 = R01 * sy, A02 = R02 * sz;
    float A10 = R10 * sx, A11 = R11 * sy, A12 = R12 * sz;
    float A20 = R20 * sx, A21 = R21 * sy, A22 = R22 * sz;
    float C00 = A00 * A00 + A01 * A01 + A02 * A02;
    float C01 = A00 * A10 + A01 * A11 + A02 * A12;
    float C02 = A00 * A20 + A01 * A21 + A02 * A22;
    float C11 = A10 * A10 + A11 * A11 + A12 * A12;
    float C12 = A10 * A20 + A11 * A21 + A12 * A22;
    float C22 = A20 * A20 + A21 * A21 + A22 * A22;

    float zc = fmaxf(m2, 1e-6f);
    float zi = 1.f / zc, zi2 = zi * zi;
    float J00 = fx * zi, J02 = -fx * m0 * zi2;
    float J11 = fy * zi, J12 = -fy * m1 * zi2;
    float t0 = J00 * C00 + J02 * C02;
    float t1 = J00 * C01 + J02 * C12;
    float t2 = J00 * C02 + J02 * C22;
    float u0 = J11 * C01 + J12 * C02;
    float u1 = J11 * C11 + J12 * C12;
    float u2 = J11 * C12 + J12 * C22;
    float c00 = t0 * J00 + t2 * J02 + 0.3f;
    float c01 = t1 * J11 + t2 * J12;
    float c10 = u0 * J00 + u2 * J02;
    float c11 = u1 * J11 + u2 * J12 + 0.3f;
    float det = fmaxf(c00 * c11 - c01 * c10, 1e-8f);
    float inv00 = c11 / det, inv11 = c00 / det, inv01 = -c01 / det;

    const float C0c = 0.28209479177387814f;
    float cr = fminf(fmaxf(shr * C0c + 0.5f, 0.f), 1.f);
    float cg = fminf(fmaxf(shg * C0c + 0.5f, 0.f), 1.f);
    float cb = fminf(fmaxf(shb * C0c + 0.5f, 0.f), 1.f);

    const float L2E = 1.4426950408889634f;
    float Aq = 0.5f * inv00 * L2E;
    float Cq = 0.5f * inv11 * L2E;
    float Bq = 0.5f * inv01 * L2E;
    float half_sum = 0.5f * (Aq + Cq);
    float half_dif = 0.5f * (Aq - Cq);
    float lam = half_sum - sqrtf(half_dif * half_dif + Bq * Bq);
    lam = fmaxf(lam, 0.f);

    float4* dst = d_attr + ((size_t)b * NN + i) * 3;
    dst[0] = make_float4(-px, -py, -Aq, -2.f * Bq);
    dst[1] = make_float4(-Cq, op, cr, cg);
    dst[2] = make_float4(cb, zz, lam, 0.f);
    d_z[b * NN + i] = zz;

    float o = fminf(fmaxf(op, 1e-6f), 1.f - 1e-6f);
    float ent = -(o * logf(o) + (1.f - o) * logf(1.f - o));

    __shared__ float red[8];
    float s = block_sum256(ent, red);
    if (threadIdx.x == 0) d_p_ent[blockIdx.y * 4 + blockIdx.x] = s;
}

// grid (BB*8) x 128: stable rank by z + scatter
__global__ void rank_kernel() {
    int b = blockIdx.x >> 3;
    int s = blockIdx.x & 7;
    __shared__ float zs[NN];
    for (int k = threadIdx.x; k < NN; k += 128) zs[k] = d_z[b * NN + k];
    __syncthreads();
    int i = s * 128 + threadIdx.x;
    float zi = zs[i];
    int rank = 0;
#pragma unroll 8
    for (int j = 0; j < NN; j++) {
        float zj = zs[j];
        rank += (zj < zi) || (zj == zi && j < i);
    }
    const float4* src = d_attr + ((size_t)b * NN + i) * 3;
    float4* dst = d_sorted + ((size_t)b * NN + rank) * 3;
    dst[0] = src[0];
    dst[1] = src[1];
    dst[2] = src[2];
}

// grid BB*SEG x 32: as-if-all-far prefix (P, S) per segment, affine warp scan
__global__ void prefix_kernel() {
    int seg = blockIdx.x;              // b*SEG + s
    int b = seg >> 3, s = seg & 7;
    int lane = threadIdx.x;
    const float4* base = d_sorted + ((size_t)b * NN + s * GPS) * 3;

    float4 p1[4], p2[4];
#pragma unroll
    for (int u = 0; u < 4; u++) {
        p1[u] = base[(lane * 4 + u) * 3 + 1];   // [h11,op,r,g]
        p2[u] = base[(lane * 4 + u) * 3 + 2];   // [b,z,lam,-]
    }
    // local (4-element) composite
    float lp = 1.f;
    float4 ls = make_float4(0.f, 0.f, 0.f, 0.f);
#pragma unroll
    for (int u = 0; u < 4; u++) {
        float a = AFARC * p1[u].y;
        float w = lp * a;
        ls.x = fmaf(w, p1[u].z, ls.x);
        ls.y = fmaf(w, p1[u].w, ls.y);
        ls.z = fmaf(w, p2[u].x, ls.z);
        ls.w = fmaf(w, p2[u].y, ls.w);
        lp *= (1.f - a);
    }
    // inclusive scan over lanes: (Pl,Sl) ∘ (Po,So) = (Pl*Po, Sl + Pl*So)
    float cp = lp;
    float4 cs = ls;
#pragma unroll
    for (int d = 1; d < 32; d <<= 1) {
        float pp = __shfl_up_sync(0xffffffffu, cp, d);
        float sx = __shfl_up_sync(0xffffffffu, cs.x, d);
        float sy = __shfl_up_sync(0xffffffffu, cs.y, d);
        float sz = __shfl_up_sync(0xffffffffu, cs.z, d);
        float sw = __shfl_up_sync(0xffffffffu, cs.w, d);
        if (lane >= d) {
            cs.x = fmaf(pp, cs.x, sx);
            cs.y = fmaf(pp, cs.y, sy);
            cs.z = fmaf(pp, cs.z, sz);
            cs.w = fmaf(pp, cs.w, sw);
            cp = pp * cp;
        }
    }
    // exclusive start for this lane
    float ep = __shfl_up_sync(0xffffffffu, cp, 1);
    float ex = __shfl_up_sync(0xffffffffu, cs.x, 1);
    float ey = __shfl_up_sync(0xffffffffu, cs.y, 1);
    float ez = __shfl_up_sync(0xffffffffu, cs.z, 1);
    float ew = __shfl_up_sync(0xffffffffu, cs.w, 1);
    if (lane == 0) { ep = 1.f; ex = ey = ez = ew = 0.f; }

    float P = ep;
    float4 S = make_float4(ex, ey, ez, ew);
    int boff = seg * (GPS + 1);
#pragma unroll
    for (int u = 0; u < 4; u++) {
        int k = lane * 4 + u;
        float invP = 1.f / P;
        d_pfPP[boff + k] = make_float2(P, invP);
        d_pfQ[boff + k] = make_float4(S.x * invP, S.y * invP, S.z * invP, S.w * invP);
        float a = AFARC * p1[u].y;
        float w = P * a;
        S.x = fmaf(w, p1[u].z, S.x);
        S.y = fmaf(w, p1[u].w, S.y);
        S.z = fmaf(w, p2[u].x, S.z);
        S.w = fmaf(w, p2[u].y, S.w);
        P *= (1.f - a);
    }
    if (lane == 31) {
        float invP = 1.f / P;
        d_pfPP[boff + GPS] = make_float2(P, invP);
        d_pfQ[boff + GPS] = make_float4(S.x * invP, S.y * invP, S.z * invP, S.w * invP);
    }
}

// grid (8, 8, BB*SEG) x 128; near gaussians explicit, far runs via prefix algebra
__global__ void render_kernel() {
    int bz = blockIdx.z;               // seg index = b*SEG + s
    int b = bz >> 3;
    int s = bz & 7;
    int t = threadIdx.x;
    int tx = t & 15, ty = t >> 4;
    int x = blockIdx.x * 16 + tx;
    int y0 = blockIdx.y * 16 + ty;
    float xf = (float)x, yf0 = (float)y0, yf1 = (float)(y0 + 8);
    u64 xp = pk2(xf, xf);
    u64 yp = pk2(yf0, yf1);

    __shared__ float4 sg[GPS * 5];          // duplicated packed layout, 10KB
    __shared__ unsigned smask[GPS / 32];    // near bits
    __shared__ float4 sQ[GPS + 1];
    __shared__ float2 sPP[GPS + 1];
    const float4* base = d_sorted + ((size_t)b * NN + s * GPS) * 3;
    {
        float4 q0 = base[t * 3 + 0];
        float4 q1 = base[t * 3 + 1];
        float4 q2 = base[t * 3 + 2];
        sg[t * 5 + 0] = make_float4(q0.x, q0.x, q0.y, q0.y);
        sg[t * 5 + 1] = make_float4(q0.z, q0.z, q0.w, q0.w);
        sg[t * 5 + 2] = make_float4(q1.x, q1.x, q1.y, q1.y);
        sg[t * 5 + 3] = make_float4(q1.z, q1.z, q1.w, q1.w);
        sg[t * 5 + 4] = make_float4(q2.x, q2.x, q2.y, q2.y);

        int boff = bz * (GPS + 1);
        sQ[t] = d_pfQ[boff + t];
        sPP[t] = d_pfPP[boff + t];
        if (t == 0) {
            sQ[GPS] = d_pfQ[boff + GPS];
            sPP[GPS] = d_pfPP[boff + GPS];
        }

        float pxx = -q0.x, pyy = -q0.y;
        float rx0 = (float)(blockIdx.x * 16), ry0 = (float)(blockIdx.y * 16);
        float dmx = fmaxf(0.f, fmaxf(rx0 - pxx, pxx - (rx0 + 15.f)));
        float dmy = fmaxf(0.f, fmaxf(ry0 - pyy, pyy - (ry0 + 15.f)));
        bool nearg = q2.z * (dmx * dmx + dmy * dmy) < 14.4269504088896f;
        unsigned bal = __ballot_sync(0xffffffffu, nearg);
        if ((t & 31) == 0) smask[t >> 5] = bal;
    }
    __syncthreads();

    u64 T = pk2(1.f, 1.f);
    u64 aR = 0ull, aG = 0ull, aB = 0ull, aD = 0ull;
    const u64 negonep = pk2(-1.f, -1.f);
    const float CLMP = -14.4269504088896f;

    unsigned mwv[4] = {smask[0], smask[1], smask[2], smask[3]};
    const ulonglong2* sp = (const ulonglong2*)sg;
    int prev = 0;
#pragma unroll
    for (int w = 0; w < 4; w++) {
        unsigned mw = mwv[w];
        while (mw) {
            int j = (w << 5) + __ffs(mw) - 1;
            mw &= mw - 1;
            if (j > prev) {
                // far run [prev, j): pixel-independent composite
                float4 Qk = sQ[j], Qi = sQ[prev];
                float Tr = sPP[j].x * sPP[prev].y;
                float dR = fmaf(Qk.x, Tr, -Qi.x);
                float dG = fmaf(Qk.y, Tr, -Qi.y);
                float dB = fmaf(Qk.z, Tr, -Qi.z);
                float dD = fmaf(Qk.w, Tr, -Qi.w);
                aR = fma2(T, pk2(dR, dR), aR);
                aG = fma2(T, pk2(dG, dG), aG);
                aB = fma2(T, pk2(dB, dB), aB);
                aD = fma2(T, pk2(dD, dD), aD);
                T = mul2(T, pk2(Tr, Tr));
            }
            // near gaussian j
            {
                ulonglong2 w0 = sp[j * 5 + 0];
                ulonglong2 w1 = sp[j * 5 + 1];
                ulonglong2 w2 = sp[j * 5 + 2];
                ulonglong2 w3 = sp[j * 5 + 3];
                ulonglong2 w4 = sp[j * 5 + 4];
                u64 dx = add2(xp, w0.x);
                u64 dy = add2(yp, w0.y);
                u64 t2 = mul2(w1.y, dy);
                u64 uu = fma2(w1.x, dx, t2);
                u64 t1 = mul2(w2.x, dy);
                u64 t1b = mul2(t1, dy);
                u64 pw = fma2(dx, uu, t1b);
                float p0, p1;
                upk2(p0, p1, pw);
                p0 = fmaxf(p0, CLMP);
                p1 = fmaxf(p1, CLMP);
                float e0, e1;
                asm("ex2.approx.f32 %0, %1;" : "=f"(e0) : "f"(p0));
                asm("ex2.approx.f32 %0, %1;" : "=f"(e1) : "f"(p1));
                u64 ep = pk2(e0, e1);
                u64 ap = mul2(ep, w2.y);
                float a0, a1;
                upk2(a0, a1, ap);
                a0 = fminf(a0, 0.99f);
                a1 = fminf(a1, 0.99f);
                u64 am = pk2(a0, a1);
                u64 wv = mul2(T, am);
                T = fma2(wv, negonep, T);
                aR = fma2(wv, w3.x, aR);
                aG = fma2(wv, w3.y, aG);
                aB = fma2(wv, w4.x, aB);
                aD = fma2(wv, w4.y, aD);
            }
            prev = j + 1;
        }
    }
    if (prev < GPS) {
        float4 Qk = sQ[GPS], Qi = sQ[prev];
        float Tr = sPP[GPS].x * sPP[prev].y;
        float dR = fmaf(Qk.x, Tr, -Qi.x);
        float dG = fmaf(Qk.y, Tr, -Qi.y);
        float dB = fmaf(Qk.z, Tr, -Qi.z);
        float dD = fmaf(Qk.w, Tr, -Qi.w);
        aR = fma2(T, pk2(dR, dR), aR);
        aG = fma2(T, pk2(dG, dG), aG);
        aB = fma2(T, pk2(dB, dB), aB);
        aD = fma2(T, pk2(dD, dD), aD);
        T = mul2(T, pk2(Tr, Tr));
    }

    float r0, r1, g0, g1, b0, b1, dd0, dd1, T0, T1;
    upk2(r0, r1, aR); upk2(g0, g1, aG); upk2(b0, b1, aB); upk2(dd0, dd1, aD); upk2(T0, T1, T);
    int segbase = bz * (HH * WW);
    int o0 = segbase + y0 * WW + x;
    int o1 = segbase + (y0 + 8) * WW + x;
    d_seg_rgbd[o0] = make_float4(r0, g0, b0, dd0);
    d_seg_rgbd[o1] = make_float4(r1, g1, b1, dd1);
    d_seg_T[o0] = T0;
    d_seg_T[o1] = T1;
}

// grid 1024 x 256: one thread per (pixel, segment); 8-lane shuffle scan merge
__global__ void merge_kernel(const float* __restrict__ target_rgb,
                             const float* __restrict__ target_depth) {
    int idx = blockIdx.x * 256 + threadIdx.x;
    int s = idx & 7;
    int g = idx >> 3;
    int hw = HH * WW;
    int b = g / hw;
    int pix = g % hw;
    int o = (b * SEG + s) * hw + pix;
    float4 c = d_seg_rgbd[o];
    float t = d_seg_T[o];

    float pre = t;
    int sub = threadIdx.x & 7;
#pragma unroll
    for (int d = 1; d < 8; d <<= 1) {
        float v = __shfl_up_sync(0xffffffffu, pre, d, 8);
        if (sub >= d) pre *= v;
    }
    float Texc = __shfl_up_sync(0xffffffffu, pre, 1, 8);
    if (sub == 0) Texc = 1.f;
    c.x *= Texc; c.y *= Texc; c.z *= Texc; c.w *= Texc;
#pragma unroll
    for (int d = 4; d; d >>= 1) {
        c.x += __shfl_down_sync(0xffffffffu, c.x, d, 8);
        c.y += __shfl_down_sync(0xffffffffu, c.y, d, 8);
        c.z += __shfl_down_sync(0xffffffffu, c.z, d, 8);
        c.w += __shfl_down_sync(0xffffffffu, c.w, d, 8);
    }

    float l1 = 0.f, l1d = 0.f;
    if (sub == 0) {
        float R = fminf(fmaxf(c.x, 0.f), 1.f);
        float G = fminf(fmaxf(c.y, 0.f), 1.f);
        float Bc = fminf(fmaxf(c.z, 0.f), 1.f);
        d_rgb[(b * 3 + 0) * hw + pix] = R;
        d_rgb[(b * 3 + 1) * hw + pix] = G;
        d_rgb[(b * 3 + 2) * hw + pix] = Bc;
        l1 = fabsf(R - target_rgb[(b * 3 + 0) * hw + pix]) +
             fabsf(G - target_rgb[(b * 3 + 1) * hw + pix]) +
             fabsf(Bc - target_rgb[(b * 3 + 2) * hw + pix]);
        l1d = fabsf(c.w - target_depth[b * hw + pix]);
    }

    __shared__ float red[8];
    float s0 = block_sum256(l1, red);
    if (threadIdx.x == 0) d_p_l1[blockIdx.x] = s0;
    float s1 = block_sum256(l1d, red);
    if (threadIdx.x == 0) d_p_l1d[blockIdx.x] = s1;
}

// grid (8, 8, BB*3) x 256: separable 7x7 SSIM via smem tiles
__global__ void ssim_kernel(const float* __restrict__ target_rgb) {
    const float GW[7] = {0.03663229f, 0.11128005f, 0.21674607f, 0.27068313f,
                         0.21674607f, 0.11128005f, 0.03663229f};
    int bc = blockIdx.z;
    int ox = blockIdx.x * 16, oy = blockIdx.y * 16;
    const float* i1 = d_rgb + (size_t)bc * HH * WW;
    const float* i2 = target_rgb + (size_t)bc * HH * WW;
    int tid = threadIdx.x;

    __shared__ float s1[22 * 22], s2[22 * 22];
    __shared__ float vm1[16 * 24], vm2[16 * 24], v11[16 * 24], v22[16 * 24], v12[16 * 24];

    for (int k = tid; k < 22 * 22; k += 256) {
        int yy = oy + k / 22 - 3;
        int xx = ox + k % 22 - 3;
        bool ok = (yy >= 0 && yy < HH && xx >= 0 && xx < WW);
        s1[k] = ok ? i1[yy * WW + xx] : 0.f;
        s2[k] = ok ? i2[yy * WW + xx] : 0.f;
    }
    __syncthreads();

    for (int k = tid; k < 16 * 22; k += 256) {
        int yy = k / 22, xx = k % 22;
        float a0 = 0.f, a1 = 0.f, a2 = 0.f, a3 = 0.f, a4 = 0.f;
#pragma unroll
        for (int tt = 0; tt < 7; tt++) {
            float w = GW[tt];
            float va = s1[(yy + tt) * 22 + xx];
            float vb = s2[(yy + tt) * 22 + xx];
            a0 = fmaf(w, va, a0);
            a1 = fmaf(w, vb, a1);
            a2 = fmaf(w * va, va, a2);
            a3 = fmaf(w * vb, vb, a3);
            a4 = fmaf(w * va, vb, a4);
        }
        int o = yy * 24 + xx;
        vm1[o] = a0; vm2[o] = a1; v11[o] = a2; v22[o] = a3; v12[o] = a4;
    }
    __syncthreads();

    int tx = tid & 15, ty = tid >> 4;
    float m1 = 0.f, m2 = 0.f, e11 = 0.f, e22 = 0.f, e12 = 0.f;
#pragma unroll
    for (int tt = 0; tt < 7; tt++) {
        float w = GW[tt];
        int o = ty * 24 + tx + tt;
        m1 = fmaf(w, vm1[o], m1);
        m2 = fmaf(w, vm2[o], m2);
        e11 = fmaf(w, v11[o], e11);
        e22 = fmaf(w, v22[o], e22);
        e12 = fmaf(w, v12[o], e12);
    }
    float sg1 = e11 - m1 * m1;
    float sg2 = e22 - m2 * m2;
    float sg12 = e12 - m1 * m2;
    const float C1 = 0.0001f, C2 = 0.0009f;
    float val = (2.f * m1 * m2 + C1) * (2.f * sg12 + C2) /
                ((m1 * m1 + m2 * m2 + C1) * (sg1 + sg2 + C2));

    __shared__ float red[8];
    float s = block_sum256(val, red);
    if (tid == 0) d_p_ssim[blockIdx.z * 64 + blockIdx.y * 8 + blockIdx.x] = s;
}

// single block 256 threads: sum partials (double accum), combine
__global__ void final_kernel(float* __restrict__ out) {
    int t = threadIdx.x;
    double a0 = 0.0, a1 = 0.0, a2 = 0.0, a3 = 0.0;
    for (int i = t; i < 1024; i += 256) { a0 += (double)d_p_l1[i]; a1 += (double)d_p_l1d[i]; }
    for (int i = t; i < 384; i += 256) a2 += (double)d_p_ssim[i];
    if (t < 8) a3 = (double)d_p_ent[t];

    __shared__ double sm0[256], sm1[256], sm2[256], sm3[256];
    sm0[t] = a0; sm1[t] = a1; sm2[t] = a2; sm3[t] = a3;
    __syncthreads();
    for (int o = 128; o; o >>= 1) {
        if (t < o) {
            sm0[t] += sm0[t + o];
            sm1[t] += sm1[t + o];
            sm2[t] += sm2[t + o];
            sm3[t] += sm3[t + o];
        }
        __syncthreads();
    }
    if (t == 0) {
        double l1rgb = sm0[0] / (double)(BB * 3 * HH * WW);
        double l1d = sm1[0] / (double)(BB * HH * WW);
        double ssim = sm2[0] / (double)(BB * 3 * HH * WW);
        double opac = sm3[0] / (double)(BB * NN);
        out[0] = (float)(0.8 * l1rgb + 0.2 * (1.0 - ssim) + 0.5 * l1d + 0.01 * opac);
    }
}

extern "C" void kernel_launch(void* const* d_in, const int* in_sizes, int n_in,
                              void* d_out, int out_size) {
    const float* gaussians = (const float*)d_in[0];
    const float* intrinsics = (const float*)d_in[1];
    const float* target_rgb = (const float*)d_in[2];
    const float* target_depth = (const float*)d_in[3];
    float* out = (float*)d_out;

    prep_kernel<<<dim3(4, BB), 256>>>(gaussians, intrinsics);
    rank_kernel<<<BB * 8, 128>>>();
    prefix_kernel<<<BB * SEG, 32>>>();
    render_kernel<<<dim3(8, 8, BB * SEG), 128>>>();
    merge_kernel<<<(BB * HH * WW * SEG) / 256, 256>>>(target_rgb, target_depth);
    ssim_kernel<<<dim3(8, 8, BB * 3), 256>>>(target_rgb);
    final_kernel<<<1, 256>>>(out);
}

// round 10
// speedup vs baseline: 1.5784x; 1.1105x over previous
#include <cuda_runtime.h>
#include <math.h>

#define BB 2
#define NN 1024
#define HH 128
#define WW 128
#define SEG 8
#define GPS (NN / SEG)   // 128 gaussians per segment

typedef unsigned long long u64;

// Scratch (static device globals — allowed)
__device__ float4 d_attr[BB * NN * 3];
__device__ float  d_z[BB * NN];
__device__ float4 d_sorted[BB * NN * 3];   // [npx,npy,h00,h01][h11,op,r,g][b,z,lam,-]
__device__ float4 d_pfQ[BB * SEG * (GPS + 1)];   // Q = S/P (as-if-all-far prefix)
__device__ float2 d_pfPP[BB * SEG * (GPS + 1)];  // (P, 1/P)
__device__ float4 d_seg_rgbd[BB * SEG * HH * WW];
__device__ float  d_seg_T[BB * SEG * HH * WW];
__device__ float  d_rgb[BB * 3 * HH * WW];
__device__ float  d_p_ent[8];
__device__ float  d_p_l1[256];
__device__ float  d_p_l1d[256];
__device__ float  d_p_ssim[384];
__device__ unsigned d_ticket;

#define AFARC 4.5399929762484854e-05f   // exp(-10)

__device__ __forceinline__ float warp_sum(float v) {
#pragma unroll
    for (int o = 16; o; o >>= 1) v += __shfl_down_sync(0xffffffffu, v, o);
    return v;
}
__device__ __forceinline__ float block_sum256(float v, float* red) {
    int lane = threadIdx.x & 31, wid = threadIdx.x >> 5;
    v = warp_sum(v);
    if (lane == 0) red[wid] = v;
    __syncthreads();
    float s = 0.f;
    if (wid == 0) {
        s = (lane < 8) ? red[lane] : 0.f;
        s = warp_sum(s);
    }
    __syncthreads();
    return s;  // valid in thread 0
}
__device__ __forceinline__ float block_sum128(float v, float* red) {
    int lane = threadIdx.x & 31, wid = threadIdx.x >> 5;
    v = warp_sum(v);
    if (lane == 0) red[wid] = v;
    __syncthreads();
    float s = 0.f;
    if (wid == 0) {
        s = (lane < 4) ? red[lane] : 0.f;
        s = warp_sum(s);
    }
    __syncthreads();
    return s;  // valid in thread 0
}

// ---- packed f32x2 helpers ----
__device__ __forceinline__ u64 pk2(float lo, float hi) {
    u64 r; asm("mov.b64 %0, {%1, %2};" : "=l"(r) : "f"(lo), "f"(hi)); return r;
}
__device__ __forceinline__ void upk2(float& lo, float& hi, u64 v) {
    asm("mov.b64 {%0, %1}, %2;" : "=f"(lo), "=f"(hi) : "l"(v));
}
__device__ __forceinline__ u64 add2(u64 a, u64 b) {
    u64 r; asm("add.rn.f32x2 %0, %1, %2;" : "=l"(r) : "l"(a), "l"(b)); return r;
}
__device__ __forceinline__ u64 mul2(u64 a, u64 b) {
    u64 r; asm("mul.rn.f32x2 %0, %1, %2;" : "=l"(r) : "l"(a), "l"(b)); return r;
}
__device__ __forceinline__ u64 fma2(u64 a, u64 b, u64 c) {
    u64 r; asm("fma.rn.f32x2 %0, %1, %2, %3;" : "=l"(r) : "l"(a), "l"(b), "l"(c)); return r;
}

// grid (4, BB) x 256
__global__ void prep_kernel(const float* __restrict__ g, const float* __restrict__ intr) {
    int b = blockIdx.y;
    int i = blockIdx.x * 256 + threadIdx.x;
    if (b == 0 && blockIdx.x == 0 && threadIdx.x == 0) d_ticket = 0u;  // reset for ssim final
    const float* gg = g + ((size_t)b * NN + i) * 38;
    float m0 = gg[0], m1 = gg[1], m2 = gg[2];
    float sx = gg[3], sy = gg[4], sz = gg[5];
    float qw = gg[6], qx = gg[7], qy = gg[8], qz = gg[9];
    float op = gg[10];
    float shr = gg[11], shg = gg[12], shb = gg[13];
    const float* I = intr + b * 9;
    float fx = I[0], cx = I[2], fy = I[4], cy = I[5];

    float zz = fmaxf(m2, 1e-4f);
    float px = fx * m0 / zz + cx;
    float py = fy * m1 / zz + cy;

    float R00 = 1.f - 2.f * (qy * qy + qz * qz), R01 = 2.f * (qx * qy - qw * qz), R02 = 2.f * (qx * qz + qw * qy);
    float R10 = 2.f * (qx * qy + qw * qz), R11 = 1.f - 2.f * (qx * qx + qz * qz), R12 = 2.f * (qy * qz - qw * qx);
    float R20 = 2.f * (qx * qz - qw * qy), R21 = 2.f * (qy * qz + qw * qx), R22 = 1.f - 2.f * (qx * qx + qy * qy);
    float A00 = R00 * sx, A01 = R01 * sy, A02 = R02 * sz;
    float A10 = R10 * sx, A11 = R11 * sy, A12 = R12 * sz;
    float A20 = R20 * sx, A21 = R21 * sy, A22 = R22 * sz;
    float C00 = A00 * A00 + A01 * A01 + A02 * A02;
    float C01 = A00 * A10 + A01 * A11 + A02 * A12;
    float C02 = A00 * A20 + A01 * A21 + A02 * A22;
    float C11 = A10 * A10 + A11 * A11 + A12 * A12;
    float C12 = A10 * A20 + A11 * A21 + A12 * A22;
    float C22 = A20 * A20 + A21 * A21 + A22 * A22;

    float zc = fmaxf(m2, 1e-6f);
    float zi = 1.f / zc, zi2 = zi * zi;
    float J00 = fx * zi, J02 = -fx * m0 * zi2;
    float J11 = fy * zi, J12 = -fy * m1 * zi2;
    float t0 = J00 * C00 + J02 * C02;
    float t1 = J00 * C01 + J02 * C12;
    float t2 = J00 * C02 + J02 * C22;
    float u0 = J11 * C01 + J12 * C02;
    float u1 = J11 * C11 + J12 * C12;
    float u2 = J11 * C12 + J12 * C22;
    float c00 = t0 * J00 + t2 * J02 + 0.3f;
    float c01 = t1 * J11 + t2 * J12;
    float c10 = u0 * J00 + u2 * J02;
    float c11 = u1 * J11 + u2 * J12 + 0.3f;
    float det = fmaxf(c00 * c11 - c01 * c10, 1e-8f);
    float inv00 = c11 / det, inv11 = c00 / det, inv01 = -c01 / det;

    const float C0c = 0.28209479177387814f;
    float cr = fminf(fmaxf(shr * C0c + 0.5f, 0.f), 1.f);
    float cg = fminf(fmaxf(shg * C0c + 0.5f, 0.f), 1.f);
    float cb = fminf(fmaxf(shb * C0c + 0.5f, 0.f), 1.f);

    const float L2E = 1.4426950408889634f;
    float Aq = 0.5f * inv00 * L2E;
    float Cq = 0.5f * inv11 * L2E;
    float Bq = 0.5f * inv01 * L2E;
    float half_sum = 0.5f * (Aq + Cq);
    float half_dif = 0.5f * (Aq - Cq);
    float lam = half_sum - sqrtf(half_dif * half_dif + Bq * Bq);
    lam = fmaxf(lam, 0.f);

    float4* dst = d_attr + ((size_t)b * NN + i) * 3;
    dst[0] = make_float4(-px, -py, -Aq, -2.f * Bq);
    dst[1] = make_float4(-Cq, op, cr, cg);
    dst[2] = make_float4(cb, zz, lam, 0.f);
    d_z[b * NN + i] = zz;

    float o = fminf(fmaxf(op, 1e-6f), 1.f - 1e-6f);
    float ent = -(o * logf(o) + (1.f - o) * logf(1.f - o));

    __shared__ float red[8];
    float s = block_sum256(ent, red);
    if (threadIdx.x == 0) d_p_ent[blockIdx.y * 4 + blockIdx.x] = s;
}

// grid (BB*8) x 128: stable rank by z + scatter
__global__ void rank_kernel() {
    int b = blockIdx.x >> 3;
    int s = blockIdx.x & 7;
    __shared__ float zs[NN];
    for (int k = threadIdx.x; k < NN; k += 128) zs[k] = d_z[b * NN + k];
    __syncthreads();
    int i = s * 128 + threadIdx.x;
    float zi = zs[i];
    int rank = 0;
#pragma unroll 8
    for (int j = 0; j < NN; j++) {
        float zj = zs[j];
        rank += (zj < zi) || (zj == zi && j < i);
    }
    const float4* src = d_attr + ((size_t)b * NN + i) * 3;
    float4* dst = d_sorted + ((size_t)b * NN + rank) * 3;
    dst[0] = src[0];
    dst[1] = src[1];
    dst[2] = src[2];
}

// grid BB*SEG x 32: as-if-all-far prefix (P, S) per segment, affine warp scan
__global__ void prefix_kernel() {
    int seg = blockIdx.x;              // b*SEG + s
    int b = seg >> 3, s = seg & 7;
    int lane = threadIdx.x;
    const float4* base = d_sorted + ((size_t)b * NN + s * GPS) * 3;

    float4 p1[4], p2[4];
#pragma unroll
    for (int u = 0; u < 4; u++) {
        p1[u] = base[(lane * 4 + u) * 3 + 1];   // [h11,op,r,g]
        p2[u] = base[(lane * 4 + u) * 3 + 2];   // [b,z,lam,-]
    }
    float lp = 1.f;
    float4 ls = make_float4(0.f, 0.f, 0.f, 0.f);
#pragma unroll
    for (int u = 0; u < 4; u++) {
        float a = AFARC * p1[u].y;
        float w = lp * a;
        ls.x = fmaf(w, p1[u].z, ls.x);
        ls.y = fmaf(w, p1[u].w, ls.y);
        ls.z = fmaf(w, p2[u].x, ls.z);
        ls.w = fmaf(w, p2[u].y, ls.w);
        lp *= (1.f - a);
    }
    float cp = lp;
    float4 cs = ls;
#pragma unroll
    for (int d = 1; d < 32; d <<= 1) {
        float pp = __shfl_up_sync(0xffffffffu, cp, d);
        float sx = __shfl_up_sync(0xffffffffu, cs.x, d);
        float sy = __shfl_up_sync(0xffffffffu, cs.y, d);
        float sz = __shfl_up_sync(0xffffffffu, cs.z, d);
        float sw = __shfl_up_sync(0xffffffffu, cs.w, d);
        if (lane >= d) {
            cs.x = fmaf(pp, cs.x, sx);
            cs.y = fmaf(pp, cs.y, sy);
            cs.z = fmaf(pp, cs.z, sz);
            cs.w = fmaf(pp, cs.w, sw);
            cp = pp * cp;
        }
    }
    float ep = __shfl_up_sync(0xffffffffu, cp, 1);
    float ex = __shfl_up_sync(0xffffffffu, cs.x, 1);
    float ey = __shfl_up_sync(0xffffffffu, cs.y, 1);
    float ez = __shfl_up_sync(0xffffffffu, cs.z, 1);
    float ew = __shfl_up_sync(0xffffffffu, cs.w, 1);
    if (lane == 0) { ep = 1.f; ex = ey = ez = ew = 0.f; }

    float P = ep;
    float4 S = make_float4(ex, ey, ez, ew);
    int boff = seg * (GPS + 1);
#pragma unroll
    for (int u = 0; u < 4; u++) {
        int k = lane * 4 + u;
        float invP = 1.f / P;
        d_pfPP[boff + k] = make_float2(P, invP);
        d_pfQ[boff + k] = make_float4(S.x * invP, S.y * invP, S.z * invP, S.w * invP);
        float a = AFARC * p1[u].y;
        float w = P * a;
        S.x = fmaf(w, p1[u].z, S.x);
        S.y = fmaf(w, p1[u].w, S.y);
        S.z = fmaf(w, p2[u].x, S.z);
        S.w = fmaf(w, p2[u].y, S.w);
        P *= (1.f - a);
    }
    if (lane == 31) {
        float invP = 1.f / P;
        d_pfPP[boff + GPS] = make_float2(P, invP);
        d_pfQ[boff + GPS] = make_float4(S.x * invP, S.y * invP, S.z * invP, S.w * invP);
    }
}

// grid (8, 8, BB*SEG) x 128; near gaussians explicit, far runs via prefix algebra
__global__ void render_kernel() {
    int bz = blockIdx.z;               // seg index = b*SEG + s
    int b = bz >> 3;
    int s = bz & 7;
    int t = threadIdx.x;
    int tx = t & 15, ty = t >> 4;
    int x = blockIdx.x * 16 + tx;
    int y0 = blockIdx.y * 16 + ty;
    float xf = (float)x, yf0 = (float)y0, yf1 = (float)(y0 + 8);
    u64 xp = pk2(xf, xf);
    u64 yp = pk2(yf0, yf1);

    __shared__ float4 sg[GPS * 5];
    __shared__ unsigned smask[GPS / 32];
    __shared__ float4 sQ[GPS + 1];
    __shared__ float2 sPP[GPS + 1];
    const float4* base = d_sorted + ((size_t)b * NN + s * GPS) * 3;
    {
        float4 q0 = base[t * 3 + 0];
        float4 q1 = base[t * 3 + 1];
        float4 q2 = base[t * 3 + 2];
        sg[t * 5 + 0] = make_float4(q0.x, q0.x, q0.y, q0.y);
        sg[t * 5 + 1] = make_float4(q0.z, q0.z, q0.w, q0.w);
        sg[t * 5 + 2] = make_float4(q1.x, q1.x, q1.y, q1.y);
        sg[t * 5 + 3] = make_float4(q1.z, q1.z, q1.w, q1.w);
        sg[t * 5 + 4] = make_float4(q2.x, q2.x, q2.y, q2.y);

        int boff = bz * (GPS + 1);
        sQ[t] = d_pfQ[boff + t];
        sPP[t] = d_pfPP[boff + t];
        if (t == 0) {
            sQ[GPS] = d_pfQ[boff + GPS];
            sPP[GPS] = d_pfPP[boff + GPS];
        }

        float pxx = -q0.x, pyy = -q0.y;
        float rx0 = (float)(blockIdx.x * 16), ry0 = (float)(blockIdx.y * 16);
        float dmx = fmaxf(0.f, fmaxf(rx0 - pxx, pxx - (rx0 + 15.f)));
        float dmy = fmaxf(0.f, fmaxf(ry0 - pyy, pyy - (ry0 + 15.f)));
        bool nearg = q2.z * (dmx * dmx + dmy * dmy) < 14.4269504088896f;
        unsigned bal = __ballot_sync(0xffffffffu, nearg);
        if ((t & 31) == 0) smask[t >> 5] = bal;
    }
    __syncthreads();

    u64 T = pk2(1.f, 1.f);
    u64 aR = 0ull, aG = 0ull, aB = 0ull, aD = 0ull;
    const u64 negonep = pk2(-1.f, -1.f);
    const float CLMP = -14.4269504088896f;

    unsigned mwv[4] = {smask[0], smask[1], smask[2], smask[3]};
    const ulonglong2* sp = (const ulonglong2*)sg;
    int prev = 0;
#pragma unroll
    for (int w = 0; w < 4; w++) {
        unsigned mw = mwv[w];
        while (mw) {
            int j = (w << 5) + __ffs(mw) - 1;
            mw &= mw - 1;
            if (j > prev) {
                float4 Qk = sQ[j], Qi = sQ[prev];
                float Tr = sPP[j].x * sPP[prev].y;
                float dR = fmaf(Qk.x, Tr, -Qi.x);
                float dG = fmaf(Qk.y, Tr, -Qi.y);
                float dB = fmaf(Qk.z, Tr, -Qi.z);
                float dD = fmaf(Qk.w, Tr, -Qi.w);
                aR = fma2(T, pk2(dR, dR), aR);
                aG = fma2(T, pk2(dG, dG), aG);
                aB = fma2(T, pk2(dB, dB), aB);
                aD = fma2(T, pk2(dD, dD), aD);
                T = mul2(T, pk2(Tr, Tr));
            }
            {
                ulonglong2 w0 = sp[j * 5 + 0];
                ulonglong2 w1 = sp[j * 5 + 1];
                ulonglong2 w2 = sp[j * 5 + 2];
                ulonglong2 w3 = sp[j * 5 + 3];
                ulonglong2 w4 = sp[j * 5 + 4];
                u64 dx = add2(xp, w0.x);
                u64 dy = add2(yp, w0.y);
                u64 t2 = mul2(w1.y, dy);
                u64 uu = fma2(w1.x, dx, t2);
                u64 t1 = mul2(w2.x, dy);
                u64 t1b = mul2(t1, dy);
                u64 pw = fma2(dx, uu, t1b);
                float p0, p1;
                upk2(p0, p1, pw);
                p0 = fmaxf(p0, CLMP);
                p1 = fmaxf(p1, CLMP);
                float e0, e1;
                asm("ex2.approx.f32 %0, %1;" : "=f"(e0) : "f"(p0));
                asm("ex2.approx.f32 %0, %1;" : "=f"(e1) : "f"(p1));
                u64 ep = pk2(e0, e1);
                u64 ap = mul2(ep, w2.y);
                float a0, a1;
                upk2(a0, a1, ap);
                a0 = fminf(a0, 0.99f);
                a1 = fminf(a1, 0.99f);
                u64 am = pk2(a0, a1);
                u64 wv = mul2(T, am);
                T = fma2(wv, negonep, T);
                aR = fma2(wv, w3.x, aR);
                aG = fma2(wv, w3.y, aG);
                aB = fma2(wv, w4.x, aB);
                aD = fma2(wv, w4.y, aD);
            }
            prev = j + 1;
        }
    }
    if (prev < GPS) {
        float4 Qk = sQ[GPS], Qi = sQ[prev];
        float Tr = sPP[GPS].x * sPP[prev].y;
        float dR = fmaf(Qk.x, Tr, -Qi.x);
        float dG = fmaf(Qk.y, Tr, -Qi.y);
        float dB = fmaf(Qk.z, Tr, -Qi.z);
        float dD = fmaf(Qk.w, Tr, -Qi.w);
        aR = fma2(T, pk2(dR, dR), aR);
        aG = fma2(T, pk2(dG, dG), aG);
        aB = fma2(T, pk2(dB, dB), aB);
        aD = fma2(T, pk2(dD, dD), aD);
        T = mul2(T, pk2(Tr, Tr));
    }

    float r0, r1, g0, g1, b0, b1, dd0, dd1, T0, T1;
    upk2(r0, r1, aR); upk2(g0, g1, aG); upk2(b0, b1, aB); upk2(dd0, dd1, aD); upk2(T0, T1, T);
    int segbase = bz * (HH * WW);
    int o0 = segbase + y0 * WW + x;
    int o1 = segbase + (y0 + 8) * WW + x;
    d_seg_rgbd[o0] = make_float4(r0, g0, b0, dd0);
    d_seg_rgbd[o1] = make_float4(r1, g1, b1, dd1);
    d_seg_T[o0] = T0;
    d_seg_T[o1] = T1;
}

// grid 256 x 128: one thread per pixel, serial 8-segment composite (16 MLP loads)
__global__ void merge_kernel(const float* __restrict__ target_rgb,
                             const float* __restrict__ target_depth) {
    int idx = blockIdx.x * 128 + threadIdx.x;
    int hw = HH * WW;
    int b = idx >> 14;                 // HW == 16384
    int pix = idx & 16383;
    int base = b * SEG * hw + pix;

    float T = 1.f, R = 0.f, G = 0.f, Bc = 0.f, D = 0.f;
#pragma unroll
    for (int s = 0; s < SEG; s++) {
        float4 c = d_seg_rgbd[base + s * hw];
        float t = d_seg_T[base + s * hw];
        R = fmaf(T, c.x, R);
        G = fmaf(T, c.y, G);
        Bc = fmaf(T, c.z, Bc);
        D = fmaf(T, c.w, D);
        T *= t;
    }
    R = fminf(fmaxf(R, 0.f), 1.f);
    G = fminf(fmaxf(G, 0.f), 1.f);
    Bc = fminf(fmaxf(Bc, 0.f), 1.f);

    d_rgb[(b * 3 + 0) * hw + pix] = R;
    d_rgb[(b * 3 + 1) * hw + pix] = G;
    d_rgb[(b * 3 + 2) * hw + pix] = Bc;

    float l1 = fabsf(R - target_rgb[(b * 3 + 0) * hw + pix]) +
               fabsf(G - target_rgb[(b * 3 + 1) * hw + pix]) +
               fabsf(Bc - target_rgb[(b * 3 + 2) * hw + pix]);
    float l1d = fabsf(D - target_depth[b * hw + pix]);

    __shared__ float red[4];
    float s0 = block_sum128(l1, red);
    if (threadIdx.x == 0) d_p_l1[blockIdx.x] = s0;
    float s1 = block_sum128(l1d, red);
    if (threadIdx.x == 0) d_p_l1d[blockIdx.x] = s1;
}

// grid (8, 8, BB*3) x 256: separable 7x7 SSIM; last block folds the final loss
__global__ void ssim_kernel(const float* __restrict__ target_rgb, float* __restrict__ out) {
    const float GW[7] = {0.03663229f, 0.11128005f, 0.21674607f, 0.27068313f,
                         0.21674607f, 0.11128005f, 0.03663229f};
    int bc = blockIdx.z;
    int ox = blockIdx.x * 16, oy = blockIdx.y * 16;
    const float* i1 = d_rgb + (size_t)bc * HH * WW;
    const float* i2 = target_rgb + (size_t)bc * HH * WW;
    int tid = threadIdx.x;

    __shared__ float s1[22 * 22], s2[22 * 22];
    __shared__ float vm1[16 * 24], vm2[16 * 24], v11[16 * 24], v22[16 * 24], v12[16 * 24];

    for (int k = tid; k < 22 * 22; k += 256) {
        int yy = oy + k / 22 - 3;
        int xx = ox + k % 22 - 3;
        bool ok = (yy >= 0 && yy < HH && xx >= 0 && xx < WW);
        s1[k] = ok ? i1[yy * WW + xx] : 0.f;
        s2[k] = ok ? i2[yy * WW + xx] : 0.f;
    }
    __syncthreads();

    for (int k = tid; k < 16 * 22; k += 256) {
        int yy = k / 22, xx = k % 22;
        float a0 = 0.f, a1 = 0.f, a2 = 0.f, a3 = 0.f, a4 = 0.f;
#pragma unroll
        for (int tt = 0; tt < 7; tt++) {
            float w = GW[tt];
            float va = s1[(yy + tt) * 22 + xx];
            float vb = s2[(yy + tt) * 22 + xx];
            a0 = fmaf(w, va, a0);
            a1 = fmaf(w, vb, a1);
            a2 = fmaf(w * va, va, a2);
            a3 = fmaf(w * vb, vb, a3);
            a4 = fmaf(w * va, vb, a4);
        }
        int o = yy * 24 + xx;
        vm1[o] = a0; vm2[o] = a1; v11[o] = a2; v22[o] = a3; v12[o] = a4;
    }
    __syncthreads();

    int tx = tid & 15, ty = tid >> 4;
    float m1 = 0.f, m2 = 0.f, e11 = 0.f, e22 = 0.f, e12 = 0.f;
#pragma unroll
    for (int tt = 0; tt < 7; tt++) {
        float w = GW[tt];
        int o = ty * 24 + tx + tt;
        m1 = fmaf(w, vm1[o], m1);
        m2 = fmaf(w, vm2[o], m2);
        e11 = fmaf(w, v11[o], e11);
        e22 = fmaf(w, v22[o], e22);
        e12 = fmaf(w, v12[o], e12);
    }
    float sg1 = e11 - m1 * m1;
    float sg2 = e22 - m2 * m2;
    float sg12 = e12 - m1 * m2;
    const float C1 = 0.0001f, C2 = 0.0009f;
    float val = (2.f * m1 * m2 + C1) * (2.f * sg12 + C2) /
                ((m1 * m1 + m2 * m2 + C1) * (sg1 + sg2 + C2));

    __shared__ float red[8];
    float s = block_sum256(val, red);

    // publish partial, grab ticket; last block computes the final loss
    __shared__ bool isLast;
    if (tid == 0) {
        d_p_ssim[blockIdx.z * 64 + blockIdx.y * 8 + blockIdx.x] = s;
        __threadfence();
        unsigned tk = atomicAdd(&d_ticket, 1u);
        isLast = (tk == 383u);
    }
    __syncthreads();
    if (!isLast) return;
    __threadfence();

    double a0 = 0.0, a1 = 0.0, a2 = 0.0, a3 = 0.0;
    for (int i = tid; i < 256; i += 256) { a0 += (double)d_p_l1[i]; a1 += (double)d_p_l1d[i]; }
    for (int i = tid; i < 384; i += 256) a2 += (double)d_p_ssim[i];
    if (tid < 8) a3 = (double)d_p_ent[tid];

    __shared__ double sm0[256], sm1[256], sm2[256], sm3[256];
    sm0[tid] = a0; sm1[tid] = a1; sm2[tid] = a2; sm3[tid] = a3;
    __syncthreads();
    for (int o = 128; o; o >>= 1) {
        if (tid < o) {
            sm0[tid] += sm0[tid + o];
            sm1[tid] += sm1[tid + o];
            sm2[tid] += sm2[tid + o];
            sm3[tid] += sm3[tid + o];
        }
        __syncthreads();
    }
    if (tid == 0) {
        double l1rgb = sm0[0] / (double)(BB * 3 * HH * WW);
        double l1d = sm1[0] / (double)(BB * HH * WW);
        double ssim = sm2[0] / (double)(BB * 3 * HH * WW);
        double opac = sm3[0] / (double)(BB * NN);
        out[0] = (float)(0.8 * l1rgb + 0.2 * (1.0 - ssim) + 0.5 * l1d + 0.01 * opac);
    }
}

extern "C" void kernel_launch(void* const* d_in, const int* in_sizes, int n_in,
                              void* d_out, int out_size) {
    const float* gaussians = (const float*)d_in[0];
    const float* intrinsics = (const float*)d_in[1];
    const float* target_rgb = (const float*)d_in[2];
    const float* target_depth = (const float*)d_in[3];
    float* out = (float*)d_out;

    prep_kernel<<<dim3(4, BB), 256>>>(gaussians, intrinsics);
    rank_kernel<<<BB * 8, 128>>>();
    prefix_kernel<<<BB * SEG, 32>>>();
    render_kernel<<<dim3(8, 8, BB * SEG), 128>>>();
    merge_kernel<<<(BB * HH * WW) / 128, 128>>>(target_rgb, target_depth);
    ssim_kernel<<<dim3(8, 8, BB * 3), 256>>>(target_rgb, out);
}